// round 13
// baseline (speedup 1.0000x reference)
#include <cuda_runtime.h>
#include <cuda_fp16.h>
#include <math.h>
#include <stdint.h>

// ---------------- problem constants ----------------
#define D_MODEL 1024
#define D_FF    4096
#define NH      16
#define DH      64
#define TOT     1024
#define BATCH   2
#define SEQ     2048
#define NTOK    (BATCH*SEQ)

// ---------------- scratch ----------------
__device__ __half g_hh  [(size_t)NTOK * D_MODEL];
__device__ __half g_qkvh[(size_t)NTOK * 3 * TOT];
__device__ __half g_attnh[(size_t)NTOK * TOT];
__device__ float  g_x2  [(size_t)NTOK * D_MODEL];
__device__ __half g_gateh[(size_t)NTOK * D_FF];
__device__ __half g_ffh [(size_t)NTOK * D_FF];
__device__ __half g_wh  [(size_t)16 * 1024 * 1024];

// ---------------- helpers ----------------
__device__ __forceinline__ void cp16(uint32_t dst, const void* src) {
    asm volatile("cp.async.cg.shared.global [%0], [%1], 16;" :: "r"(dst), "l"(src));
}
__device__ __forceinline__ float ex2(float x) {
    float r;
    asm("ex2.approx.ftz.f32 %0, %1;" : "=f"(r) : "f"(x));
    return r;
}
__device__ __forceinline__ uint32_t packh2(float lo, float hi) {
    __half2 h = __floats2half2_rn(lo, hi);
    return *reinterpret_cast<uint32_t*>(&h);
}
__device__ __forceinline__ uint32_t scaleh2(uint32_t w, float sc) {
    __half2 h = *reinterpret_cast<__half2*>(&w);
    float2 f = __half22float2(h);
    return packh2(f.x * sc, f.y * sc);
}
__device__ __forceinline__ void mma_f16(float& c0, float& c1, float& c2, float& c3,
                                        uint32_t a0, uint32_t a1, uint32_t a2, uint32_t a3,
                                        uint32_t b0, uint32_t b1) {
    asm volatile(
        "mma.sync.aligned.m16n8k16.row.col.f32.f16.f16.f32 "
        "{%0,%1,%2,%3}, {%4,%5,%6,%7}, {%8,%9}, {%0,%1,%2,%3};"
        : "+f"(c0), "+f"(c1), "+f"(c2), "+f"(c3)
        : "r"(a0), "r"(a1), "r"(a2), "r"(a3), "r"(b0), "r"(b1));
}
__device__ __forceinline__ void ldsm_x4(uint32_t& r0, uint32_t& r1, uint32_t& r2, uint32_t& r3,
                                        uint32_t addr) {
    asm volatile("ldmatrix.sync.aligned.m8n8.x4.shared.b16 {%0,%1,%2,%3}, [%4];"
                 : "=r"(r0), "=r"(r1), "=r"(r2), "=r"(r3) : "r"(addr));
}
__device__ __forceinline__ void ldsm_x4_t(uint32_t& r0, uint32_t& r1, uint32_t& r2, uint32_t& r3,
                                          uint32_t addr) {
    asm volatile("ldmatrix.sync.aligned.m8n8.x4.trans.shared.b16 {%0,%1,%2,%3}, [%4];"
                 : "=r"(r0), "=r"(r1), "=r"(r2), "=r"(r3) : "r"(addr));
}

// ---------------- block reduction ----------------
__device__ __forceinline__ float block_reduce_sum(float v) {
    __shared__ float sh[33];
    int lane = threadIdx.x & 31, wid = threadIdx.x >> 5;
    #pragma unroll
    for (int o = 16; o; o >>= 1) v += __shfl_xor_sync(0xffffffffu, v, o);
    if (lane == 0) sh[wid] = v;
    __syncthreads();
    if (wid == 0) {
        v = (lane < (blockDim.x >> 5)) ? sh[lane] : 0.f;
        #pragma unroll
        for (int o = 16; o; o >>= 1) v += __shfl_xor_sync(0xffffffffu, v, o);
        if (lane == 0) sh[32] = v;
    }
    __syncthreads();
    float r = sh[32];
    __syncthreads();
    return r;
}

// ---------------- all weights fp32 -> fp16, one launch ----------------
__global__ void to_half_all(const float* __restrict__ wqkv, const float* __restrict__ wout,
                            const float* __restrict__ wgate, const float* __restrict__ wup,
                            const float* __restrict__ wdown, __half* __restrict__ out) {
    int idx = blockIdx.x * blockDim.x + threadIdx.x;
    const int stride = gridDim.x * blockDim.x;
    for (; idx < 4 * 1024 * 1024; idx += stride) {
        const float* src;
        size_t local, ob;
        if (idx < 768 * 1024)            { src = wqkv;  local = idx;                ob = 0; }
        else if (idx < 1024 * 1024)      { src = wout;  local = idx - 768 * 1024;   ob = (size_t)3 * 1024 * 1024; }
        else if (idx < 2 * 1024 * 1024)  { src = wgate; local = idx - 1024 * 1024;  ob = (size_t)4 * 1024 * 1024; }
        else if (idx < 3 * 1024 * 1024)  { src = wup;   local = idx - 2 * 1024 * 1024; ob = (size_t)8 * 1024 * 1024; }
        else                             { src = wdown; local = idx - 3 * 1024 * 1024; ob = (size_t)12 * 1024 * 1024; }
        float4 v = ((const float4*)src)[local];
        __half2* o2 = (__half2*)(out + ob);
        o2[local * 2    ] = __floats2half2_rn(v.x, v.y);
        o2[local * 2 + 1] = __floats2half2_rn(v.z, v.w);
    }
}

// ---------------- RMSNorm -> fp16 ----------------
__global__ void rmsnorm_kernel(const float* __restrict__ x,
                               const float* __restrict__ w,
                               __half* __restrict__ o) {
    const size_t base = (size_t)blockIdx.x * D_MODEL;
    float ss = 0.f;
    for (int i = threadIdx.x; i < D_MODEL; i += 256) {
        float v = x[base + i];
        ss += v * v;
    }
    ss = block_reduce_sum(ss);
    float r = rsqrtf(ss * (1.0f / D_MODEL) + 1e-6f);
    for (int i = threadIdx.x; i < D_MODEL; i += 256)
        o[base + i] = __float2half_rn(x[base + i] * r * w[i]);
}

// ---------------- RoPE in-place on fp16 qkv ----------------
__global__ void rope_kernel(__half* __restrict__ qkv) {
    const int t   = blockIdx.x;
    const int pos = t & (SEQ - 1);
    const int h   = threadIdx.x >> 5;
    const int i   = threadIdx.x & 31;
    float invf = expf(-(2.0f * (float)i / (float)DH) * logf(10000.0f));
    float fr = (float)pos * invf;
    float s, c;
    sincosf(fr, &s, &c);
    __half* q = qkv + (size_t)t * (3 * TOT) + h * DH;
    float q1 = __half2float(q[i]), q2 = __half2float(q[i + 32]);
    q[i]      = __float2half_rn(q1 * c - q2 * s);
    q[i + 32] = __float2half_rn(q2 * c + q1 * s);
    __half* k = q + TOT;
    float k1 = __half2float(k[i]), k2 = __half2float(k[i + 32]);
    k[i]      = __float2half_rn(k1 * c - k2 * s);
    k[i + 32] = __float2half_rn(k2 * c + k1 * s);
}

// ---------------- FP16 mma GEMM, BK=64, 3-stage, ldmatrix ----------------
// BM = 32*MFRAG (2 M-warps x 4 N-warps, warp tile (16*MFRAG) x 32), BN=128.
// EPI 0: fp32 plain  EPI 1: fp16 store  EPI 2: fp32 + X residual
// EPI 3: fp16 store of silu(Xh)*acc (X is fp16 gate)
#define EPI_PLAIN  0
#define EPI_HALF   1
#define EPI_RES    2
#define EPI_SWIGLU 3

#define PW 36
#define GEMM_SMEM(BM) (3 * ((BM) + 128) * PW * 4)

template<int EPI, int MFRAG>
__global__ void __launch_bounds__(256, 2)
gemm_f16(const __half* __restrict__ A, int lda,
         const __half* __restrict__ B, int ldb,
         void* __restrict__ Cv, int ldc,
         const void* __restrict__ X, int K) {
    constexpr int BM = 32 * MFRAG;
    constexpr int ASTG = BM * PW;          // words per A stage
    constexpr int BSTG = 128 * PW;
    extern __shared__ uint32_t smw[];
    uint32_t* As = smw;
    uint32_t* Bs = smw + 3 * ASTG;

    const int tid  = threadIdx.x;
    const int lane = tid & 31;
    const int wid  = tid >> 5;
    const int wm_base = (wid >> 2) * (16 * MFRAG);
    const int wn_base = (wid & 3) * 32;
    const int m0 = blockIdx.y * BM, n0 = blockIdx.x * 128;
    const int lr = lane >> 2, lc = lane & 3;

    const int a_off = (lane & 15) * PW + (lane >> 4) * 4;
    const int b_off = ((lane & 7) + ((lane >> 4) << 3)) * PW + (((lane >> 3) & 1) * 4);

    float acc[MFRAG][4][4];
    #pragma unroll
    for (int i = 0; i < MFRAG; i++)
        #pragma unroll
        for (int j = 0; j < 4; j++)
            #pragma unroll
            for (int r = 0; r < 4; r++) acc[i][j][r] = 0.f;

    const int nt = K / 64;

    auto load_tile = [&](int stg, int kt) {
        uint32_t as_u = (uint32_t)__cvta_generic_to_shared(As + stg * ASTG);
        uint32_t bs_u = (uint32_t)__cvta_generic_to_shared(Bs + stg * BSTG);
        #pragma unroll
        for (int i = 0; i < BM / 32; i++) {
            int c = tid + i * 256, row = c >> 3, sub = c & 7;
            cp16(as_u + (uint32_t)(row * PW + sub * 4) * 4,
                 A + (size_t)(m0 + row) * lda + kt + sub * 8);
        }
        #pragma unroll
        for (int i = 0; i < 4; i++) {
            int c = tid + i * 256, row = c >> 3, sub = c & 7;
            cp16(bs_u + (uint32_t)(row * PW + sub * 4) * 4,
                 B + (size_t)(n0 + row) * ldb + kt + sub * 8);
        }
        asm volatile("cp.async.commit_group;");
    };

    load_tile(0, 0);
    if (nt > 1) load_tile(1, 64);

    for (int t = 0; t < nt; t++) {
        if (t + 1 < nt) asm volatile("cp.async.wait_group 1;");
        else            asm volatile("cp.async.wait_group 0;");
        __syncthreads();
        if (t + 2 < nt) load_tile((t + 2) % 3, (t + 2) * 64);

        const uint32_t as_u = (uint32_t)__cvta_generic_to_shared(As + (t % 3) * ASTG);
        const uint32_t bs_u = (uint32_t)__cvta_generic_to_shared(Bs + (t % 3) * BSTG);
        #pragma unroll
        for (int ks = 0; ks < 4; ks++) {
            const int kw = ks * 8;
            uint32_t af[MFRAG][4];
            uint32_t bf[4][2];
            #pragma unroll
            for (int mi = 0; mi < MFRAG; mi++)
                ldsm_x4(af[mi][0], af[mi][1], af[mi][2], af[mi][3],
                        as_u + (uint32_t)((wm_base + mi * 16) * PW + kw + a_off) * 4);
            #pragma unroll
            for (int njp = 0; njp < 2; njp++)
                ldsm_x4(bf[2*njp][0], bf[2*njp][1], bf[2*njp+1][0], bf[2*njp+1][1],
                        bs_u + (uint32_t)((wn_base + njp * 16) * PW + kw + b_off) * 4);
            #pragma unroll
            for (int mi = 0; mi < MFRAG; mi++)
                #pragma unroll
                for (int nj = 0; nj < 4; nj++)
                    mma_f16(acc[mi][nj][0], acc[mi][nj][1], acc[mi][nj][2], acc[mi][nj][3],
                            af[mi][0], af[mi][1], af[mi][2], af[mi][3],
                            bf[nj][0], bf[nj][1]);
        }
        __syncthreads();
    }

    #pragma unroll
    for (int mi = 0; mi < MFRAG; mi++) {
        int gm = m0 + wm_base + mi * 16 + lr;
        #pragma unroll
        for (int nj = 0; nj < 4; nj++) {
            int gn = n0 + wn_base + nj * 8 + 2 * lc;
            float2 v0 = make_float2(acc[mi][nj][0], acc[mi][nj][1]);
            float2 v1 = make_float2(acc[mi][nj][2], acc[mi][nj][3]);
            if (EPI == EPI_RES) {
                const float* Xf = (const float*)X;
                float2 r0 = *(const float2*)(Xf + (size_t)gm * ldc + gn);
                float2 r1 = *(const float2*)(Xf + (size_t)(gm + 8) * ldc + gn);
                v0.x += r0.x; v0.y += r0.y;
                v1.x += r1.x; v1.y += r1.y;
                float* C = (float*)Cv;
                *(float2*)(C + (size_t)gm * ldc + gn) = v0;
                *(float2*)(C + (size_t)(gm + 8) * ldc + gn) = v1;
            } else if (EPI == EPI_SWIGLU) {
                const __half* Xh = (const __half*)X;
                float2 g0 = __half22float2(*(const __half2*)(Xh + (size_t)gm * ldc + gn));
                float2 g1 = __half22float2(*(const __half2*)(Xh + (size_t)(gm + 8) * ldc + gn));
                __half* Ch = (__half*)Cv;
                *(__half2*)(Ch + (size_t)gm * ldc + gn) =
                    __floats2half2_rn(g0.x / (1.f + __expf(-g0.x)) * v0.x,
                                      g0.y / (1.f + __expf(-g0.y)) * v0.y);
                *(__half2*)(Ch + (size_t)(gm + 8) * ldc + gn) =
                    __floats2half2_rn(g1.x / (1.f + __expf(-g1.x)) * v1.x,
                                      g1.y / (1.f + __expf(-g1.y)) * v1.y);
            } else if (EPI == EPI_HALF) {
                __half* Ch = (__half*)Cv;
                *(__half2*)(Ch + (size_t)gm * ldc + gn) = __floats2half2_rn(v0.x, v0.y);
                *(__half2*)(Ch + (size_t)(gm + 8) * ldc + gn) = __floats2half2_rn(v1.x, v1.y);
            } else {
                float* C = (float*)Cv;
                *(float2*)(C + (size_t)gm * ldc + gn) = v0;
                *(float2*)(C + (size_t)(gm + 8) * ldc + gn) = v1;
            }
        }
    }
}

// ---------------- FP16 Flash attention, ldmatrix loads ----------------
#define FKPW 36
#define FTILE_W (64 * FKPW)
#define FLASH_SMEM (4 * FTILE_W * 4)   // 36 KB

__global__ void __launch_bounds__(256, 2)
flash_kernel(const __half* __restrict__ qkv, __half* __restrict__ attn) {
    extern __shared__ uint32_t smf[];
    uint32_t* Ks = smf;
    uint32_t* Vs = smf + 2 * FTILE_W;

    // reverse q-block order: heavy (large by) CTAs launch first
    const int by = (int)gridDim.x - 1 - (int)blockIdx.x;
    const int z  = blockIdx.y;
    const int b = z >> 4, h = z & 15;
    const int tid = threadIdx.x, lane = tid & 31, w = tid >> 5;
    const int lr = lane >> 2, lc = lane & 3;

    const __half* Qb = qkv + (size_t)b * SEQ * 3 * TOT + h * DH;
    const __half* Kb = Qb + TOT;
    const __half* Vb = Qb + 2 * TOT;
    const int q0 = by * 128 + w * 16;

    const int kb_off = ((lane & 7) + ((lane >> 4) << 3)) * FKPW + (((lane >> 3) & 1) * 4);
    const int v_off_h = (lane & 15) * 72 + (lane >> 4) * 8;

    const float sc = 0.18033688011f;
    uint32_t qf[4][4];
    {
        const __half* r0 = Qb + (size_t)(q0 + lr) * 3072;
        const __half* r1 = Qb + (size_t)(q0 + lr + 8) * 3072;
        #pragma unroll
        for (int ks = 0; ks < 4; ks++) {
            qf[ks][0] = scaleh2(*(const uint32_t*)(r0 + ks * 16 + 2 * lc    ), sc);
            qf[ks][1] = scaleh2(*(const uint32_t*)(r1 + ks * 16 + 2 * lc    ), sc);
            qf[ks][2] = scaleh2(*(const uint32_t*)(r0 + ks * 16 + 8 + 2 * lc), sc);
            qf[ks][3] = scaleh2(*(const uint32_t*)(r1 + ks * 16 + 8 + 2 * lc), sc);
        }
    }

    float m0 = -1e30f, m8 = -1e30f, l0 = 0.f, l8 = 0.f;
    float o[8][4];
    #pragma unroll
    for (int nd = 0; nd < 8; nd++)
        #pragma unroll
        for (int r = 0; r < 4; r++) o[nd][r] = 0.f;

    const int nt = 2 * by + 2;

    auto load_kv = [&](int t) {
        int buf = t & 1;
        uint32_t ku = (uint32_t)__cvta_generic_to_shared(Ks + buf * FTILE_W);
        uint32_t vu = (uint32_t)__cvta_generic_to_shared(Vs + buf * FTILE_W);
        int kv0 = t * 64;
        #pragma unroll
        for (int i = 0; i < 2; i++) {
            int c = tid + i * 256, r = c >> 3, cc = c & 7;
            uint32_t so = (uint32_t)(r * FKPW + cc * 4) * 4;
            cp16(ku + so, Kb + (size_t)(kv0 + r) * 3072 + cc * 8);
            cp16(vu + so, Vb + (size_t)(kv0 + r) * 3072 + cc * 8);
        }
        asm volatile("cp.async.commit_group;");
    };

    load_kv(0);

    for (int t = 0; t < nt; t++) {
        asm volatile("cp.async.wait_group 0;");
        __syncthreads();
        if (t + 1 < nt) load_kv(t + 1);

        const uint32_t ks_u = (uint32_t)__cvta_generic_to_shared(Ks + (t & 1) * FTILE_W);
        const uint32_t vs_u = (uint32_t)__cvta_generic_to_shared(Vs + (t & 1) * FTILE_W);

        float s[8][4];
        #pragma unroll
        for (int nj = 0; nj < 8; nj++)
            #pragma unroll
            for (int r = 0; r < 4; r++) s[nj][r] = 0.f;
        #pragma unroll
        for (int ks = 0; ks < 4; ks++) {
            const int kw = ks * 8;
            #pragma unroll
            for (int njp = 0; njp < 4; njp++) {
                uint32_t b00, b01, b10, b11;
                ldsm_x4(b00, b01, b10, b11,
                        ks_u + (uint32_t)(njp * 16 * FKPW + kw + kb_off) * 4);
                mma_f16(s[2*njp  ][0], s[2*njp  ][1], s[2*njp  ][2], s[2*njp  ][3],
                        qf[ks][0], qf[ks][1], qf[ks][2], qf[ks][3], b00, b01);
                mma_f16(s[2*njp+1][0], s[2*njp+1][1], s[2*njp+1][2], s[2*njp+1][3],
                        qf[ks][0], qf[ks][1], qf[ks][2], qf[ks][3], b10, b11);
            }
        }

        if (t >= 2 * by) {
            const int i0 = q0 + lr, i8 = i0 + 8;
            const int cb = t * 64;
            #pragma unroll
            for (int nj = 0; nj < 8; nj++) {
                int j0 = cb + nj * 8 + 2 * lc;
                if (j0     > i0) s[nj][0] = -1e30f;
                if (j0 + 1 > i0) s[nj][1] = -1e30f;
                if (j0     > i8) s[nj][2] = -1e30f;
                if (j0 + 1 > i8) s[nj][3] = -1e30f;
            }
        }

        float mx0 = -1e30f, mx8 = -1e30f;
        #pragma unroll
        for (int nj = 0; nj < 8; nj++) {
            mx0 = fmaxf(mx0, fmaxf(s[nj][0], s[nj][1]));
            mx8 = fmaxf(mx8, fmaxf(s[nj][2], s[nj][3]));
        }
        mx0 = fmaxf(mx0, __shfl_xor_sync(0xffffffffu, mx0, 1));
        mx0 = fmaxf(mx0, __shfl_xor_sync(0xffffffffu, mx0, 2));
        mx8 = fmaxf(mx8, __shfl_xor_sync(0xffffffffu, mx8, 1));
        mx8 = fmaxf(mx8, __shfl_xor_sync(0xffffffffu, mx8, 2));

        float mn0 = fmaxf(m0, mx0), mn8 = fmaxf(m8, mx8);
        float es0 = ex2(m0 - mn0), es8 = ex2(m8 - mn8);
        m0 = mn0; m8 = mn8;

        float sum0 = 0.f, sum8 = 0.f;
        #pragma unroll
        for (int nj = 0; nj < 8; nj++) {
            s[nj][0] = ex2(s[nj][0] - mn0);
            s[nj][1] = ex2(s[nj][1] - mn0);
            s[nj][2] = ex2(s[nj][2] - mn8);
            s[nj][3] = ex2(s[nj][3] - mn8);
            sum0 += s[nj][0] + s[nj][1];
            sum8 += s[nj][2] + s[nj][3];
        }
        sum0 += __shfl_xor_sync(0xffffffffu, sum0, 1);
        sum0 += __shfl_xor_sync(0xffffffffu, sum0, 2);
        sum8 += __shfl_xor_sync(0xffffffffu, sum8, 1);
        sum8 += __shfl_xor_sync(0xffffffffu, sum8, 2);
        l0 = l0 * es0 + sum0;
        l8 = l8 * es8 + sum8;

        #pragma unroll
        for (int nd = 0; nd < 8; nd++) {
            o[nd][0] *= es0; o[nd][1] *= es0;
            o[nd][2] *= es8; o[nd][3] *= es8;
        }

        #pragma unroll
        for (int tt = 0; tt < 4; tt++) {
            uint32_t a0 = packh2(s[2*tt    ][0], s[2*tt    ][1]);
            uint32_t a1 = packh2(s[2*tt    ][2], s[2*tt    ][3]);
            uint32_t a2 = packh2(s[2*tt + 1][0], s[2*tt + 1][1]);
            uint32_t a3 = packh2(s[2*tt + 1][2], s[2*tt + 1][3]);
            #pragma unroll
            for (int ndp = 0; ndp < 4; ndp++) {
                uint32_t b00, b01, b10, b11;
                ldsm_x4_t(b00, b01, b10, b11,
                          vs_u + (uint32_t)(tt * 16 * 72 + ndp * 16 + v_off_h) * 2);
                mma_f16(o[2*ndp  ][0], o[2*ndp  ][1], o[2*ndp  ][2], o[2*ndp  ][3],
                        a0, a1, a2, a3, b00, b01);
                mma_f16(o[2*ndp+1][0], o[2*ndp+1][1], o[2*ndp+1][2], o[2*ndp+1][3],
                        a0, a1, a2, a3, b10, b11);
            }
        }
        __syncthreads();
    }

    const float inv0 = 1.f / l0, inv8 = 1.f / l8;
    const size_t trow = (size_t)b * SEQ + q0;
    __half* ob0 = attn + (trow + lr    ) * TOT + h * DH;
    __half* ob8 = attn + (trow + lr + 8) * TOT + h * DH;
    #pragma unroll
    for (int nd = 0; nd < 8; nd++) {
        int col = nd * 8 + 2 * lc;
        *(__half2*)(ob0 + col) = __floats2half2_rn(o[nd][0] * inv0, o[nd][1] * inv0);
        *(__half2*)(ob8 + col) = __floats2half2_rn(o[nd][2] * inv8, o[nd][3] * inv8);
    }
}

// ---------------- launch ----------------
extern "C" void kernel_launch(void* const* d_in, const int* in_sizes, int n_in,
                              void* d_out, int out_size) {
    const float* x      = (const float*)d_in[0];
    const float* w_ln1  = (const float*)d_in[1];
    const float* w_qkv  = (const float*)d_in[2];
    const float* w_out  = (const float*)d_in[3];
    const float* w_ln2  = (const float*)d_in[4];
    const float* w_gate = (const float*)d_in[5];
    const float* w_up   = (const float*)d_in[6];
    const float* w_down = (const float*)d_in[7];
    float* out = (float*)d_out;

    void* p;
    cudaGetSymbolAddress(&p, g_hh);    __half* h    = (__half*)p;
    cudaGetSymbolAddress(&p, g_qkvh);  __half* qkv  = (__half*)p;
    cudaGetSymbolAddress(&p, g_attnh); __half* attn = (__half*)p;
    cudaGetSymbolAddress(&p, g_x2);    float*  x2   = (float*)p;
    cudaGetSymbolAddress(&p, g_gateh); __half* gateh= (__half*)p;
    cudaGetSymbolAddress(&p, g_ffh);   __half* ffh  = (__half*)p;
    cudaGetSymbolAddress(&p, g_wh);    __half* wh   = (__half*)p;

    __half* wqkv_h  = wh;
    __half* wout_h  = wqkv_h + 3*1024*1024;
    __half* wgate_h = wout_h + 1024*1024;
    __half* wup_h   = wgate_h + 4*1024*1024;
    __half* wdown_h = wup_h + 4*1024*1024;

    constexpr int SM128 = GEMM_SMEM(128);
    constexpr int SM64  = GEMM_SMEM(64);
    cudaFuncSetAttribute(gemm_f16<EPI_HALF,4>,   cudaFuncAttributeMaxDynamicSharedMemorySize, SM128);
    cudaFuncSetAttribute(gemm_f16<EPI_HALF,4>,   cudaFuncAttributeMaxDynamicSharedMemorySize, SM128);
    cudaFuncSetAttribute(gemm_f16<EPI_SWIGLU,4>, cudaFuncAttributeMaxDynamicSharedMemorySize, SM128);
    cudaFuncSetAttribute(gemm_f16<EPI_RES,2>,    cudaFuncAttributeMaxDynamicSharedMemorySize, SM64);
    cudaFuncSetAttribute(flash_kernel, cudaFuncAttributeMaxDynamicSharedMemorySize, FLASH_SMEM);

    // 0) convert all weights to fp16
    to_half_all<<<512, 256>>>(w_qkv, w_out, w_gate, w_up, w_down, wh);

    // 1) h = rmsnorm(x, w_ln1) -> fp16
    rmsnorm_kernel<<<NTOK, 256>>>(x, w_ln1, h);

    // 2) qkv = h @ w_qkv^T -> fp16
    gemm_f16<EPI_HALF,4><<<dim3(3*TOT/128, NTOK/128), 256, SM128>>>(
        h, D_MODEL, wqkv_h, D_MODEL, qkv, 3*TOT, nullptr, D_MODEL);

    // 3) RoPE (fp16 in-place)
    rope_kernel<<<NTOK, 512>>>(qkv);

    // 4) flash attention -> attn (fp16)
    flash_kernel<<<dim3(SEQ/128, BATCH*NH), 256, FLASH_SMEM>>>(qkv, attn);

    // 5) x2 = x + attn @ w_out^T   (BM=64: 512 CTAs, full occupancy)
    gemm_f16<EPI_RES,2><<<dim3(D_MODEL/128, NTOK/64), 256, SM64>>>(
        attn, TOT, wout_h, TOT, x2, D_MODEL, x, TOT);

    // 6) h = rmsnorm(x2, w_ln2) -> fp16
    rmsnorm_kernel<<<NTOK, 256>>>(x2, w_ln2, h);

    // 7) gate = h @ w_gate^T -> fp16; up-proj fused SwiGLU -> ffh (fp16)
    gemm_f16<EPI_HALF,4><<<dim3(D_FF/128, NTOK/128), 256, SM128>>>(
        h, D_MODEL, wgate_h, D_MODEL, gateh, D_FF, nullptr, D_MODEL);
    gemm_f16<EPI_SWIGLU,4><<<dim3(D_FF/128, NTOK/128), 256, SM128>>>(
        h, D_MODEL, wup_h, D_MODEL, ffh, D_FF, gateh, D_MODEL);

    // 8) out = x2 + ffh @ w_down^T   (BM=64)
    gemm_f16<EPI_RES,2><<<dim3(D_MODEL/128, NTOK/64), 256, SM64>>>(
        ffh, D_FF, wdown_h, D_FF, out, D_MODEL, x2, D_FF);
}

// round 15
// speedup vs baseline: 1.0697x; 1.0697x over previous
#include <cuda_runtime.h>
#include <cuda_fp16.h>
#include <math.h>
#include <stdint.h>

// ---------------- problem constants ----------------
#define D_MODEL 1024
#define D_FF    4096
#define NH      16
#define DH      64
#define TOT     1024
#define BATCH   2
#define SEQ     2048
#define NTOK    (BATCH*SEQ)

// ---------------- scratch ----------------
__device__ __half g_hh  [(size_t)NTOK * D_MODEL];
__device__ __half g_qkvh[(size_t)NTOK * 3 * TOT];
__device__ __half g_attnh[(size_t)NTOK * TOT];
__device__ float  g_x2  [(size_t)NTOK * D_MODEL];
__device__ __half g_gateh[(size_t)NTOK * D_FF];
__device__ __half g_ffh [(size_t)NTOK * D_FF];
__device__ __half g_wh  [(size_t)16 * 1024 * 1024];

// ---------------- helpers ----------------
__device__ __forceinline__ void cp16(uint32_t dst, const void* src) {
    asm volatile("cp.async.cg.shared.global [%0], [%1], 16;" :: "r"(dst), "l"(src));
}
__device__ __forceinline__ float ex2(float x) {
    float r;
    asm("ex2.approx.ftz.f32 %0, %1;" : "=f"(r) : "f"(x));
    return r;
}
__device__ __forceinline__ uint32_t packh2(float lo, float hi) {
    __half2 h = __floats2half2_rn(lo, hi);
    return *reinterpret_cast<uint32_t*>(&h);
}
__device__ __forceinline__ uint32_t scaleh2(uint32_t w, float sc) {
    __half2 h = *reinterpret_cast<__half2*>(&w);
    float2 f = __half22float2(h);
    return packh2(f.x * sc, f.y * sc);
}
__device__ __forceinline__ void mma_f16(float& c0, float& c1, float& c2, float& c3,
                                        uint32_t a0, uint32_t a1, uint32_t a2, uint32_t a3,
                                        uint32_t b0, uint32_t b1) {
    asm volatile(
        "mma.sync.aligned.m16n8k16.row.col.f32.f16.f16.f32 "
        "{%0,%1,%2,%3}, {%4,%5,%6,%7}, {%8,%9}, {%0,%1,%2,%3};"
        : "+f"(c0), "+f"(c1), "+f"(c2), "+f"(c3)
        : "r"(a0), "r"(a1), "r"(a2), "r"(a3), "r"(b0), "r"(b1));
}
__device__ __forceinline__ void ldsm_x4(uint32_t& r0, uint32_t& r1, uint32_t& r2, uint32_t& r3,
                                        uint32_t addr) {
    asm volatile("ldmatrix.sync.aligned.m8n8.x4.shared.b16 {%0,%1,%2,%3}, [%4];"
                 : "=r"(r0), "=r"(r1), "=r"(r2), "=r"(r3) : "r"(addr));
}
__device__ __forceinline__ void ldsm_x4_t(uint32_t& r0, uint32_t& r1, uint32_t& r2, uint32_t& r3,
                                          uint32_t addr) {
    asm volatile("ldmatrix.sync.aligned.m8n8.x4.trans.shared.b16 {%0,%1,%2,%3}, [%4];"
                 : "=r"(r0), "=r"(r1), "=r"(r2), "=r"(r3) : "r"(addr));
}

// ---------------- block reduction ----------------
__device__ __forceinline__ float block_reduce_sum(float v) {
    __shared__ float sh[33];
    int lane = threadIdx.x & 31, wid = threadIdx.x >> 5;
    #pragma unroll
    for (int o = 16; o; o >>= 1) v += __shfl_xor_sync(0xffffffffu, v, o);
    if (lane == 0) sh[wid] = v;
    __syncthreads();
    if (wid == 0) {
        v = (lane < (blockDim.x >> 5)) ? sh[lane] : 0.f;
        #pragma unroll
        for (int o = 16; o; o >>= 1) v += __shfl_xor_sync(0xffffffffu, v, o);
        if (lane == 0) sh[32] = v;
    }
    __syncthreads();
    float r = sh[32];
    __syncthreads();
    return r;
}

// ---------------- all weights fp32 -> fp16, one launch ----------------
__global__ void to_half_all(const float* __restrict__ wqkv, const float* __restrict__ wout,
                            const float* __restrict__ wgate, const float* __restrict__ wup,
                            const float* __restrict__ wdown, __half* __restrict__ out) {
    int idx = blockIdx.x * blockDim.x + threadIdx.x;
    const int stride = gridDim.x * blockDim.x;
    for (; idx < 4 * 1024 * 1024; idx += stride) {
        const float* src;
        size_t local, ob;
        if (idx < 768 * 1024)            { src = wqkv;  local = idx;                ob = 0; }
        else if (idx < 1024 * 1024)      { src = wout;  local = idx - 768 * 1024;   ob = (size_t)3 * 1024 * 1024; }
        else if (idx < 2 * 1024 * 1024)  { src = wgate; local = idx - 1024 * 1024;  ob = (size_t)4 * 1024 * 1024; }
        else if (idx < 3 * 1024 * 1024)  { src = wup;   local = idx - 2 * 1024 * 1024; ob = (size_t)8 * 1024 * 1024; }
        else                             { src = wdown; local = idx - 3 * 1024 * 1024; ob = (size_t)12 * 1024 * 1024; }
        float4 v = ((const float4*)src)[local];
        __half2* o2 = (__half2*)(out + ob);
        o2[local * 2    ] = __floats2half2_rn(v.x, v.y);
        o2[local * 2 + 1] = __floats2half2_rn(v.z, v.w);
    }
}

// ---------------- RMSNorm -> fp16 ----------------
__global__ void rmsnorm_kernel(const float* __restrict__ x,
                               const float* __restrict__ w,
                               __half* __restrict__ o) {
    const size_t base = (size_t)blockIdx.x * D_MODEL;
    float ss = 0.f;
    for (int i = threadIdx.x; i < D_MODEL; i += 256) {
        float v = x[base + i];
        ss += v * v;
    }
    ss = block_reduce_sum(ss);
    float r = rsqrtf(ss * (1.0f / D_MODEL) + 1e-6f);
    for (int i = threadIdx.x; i < D_MODEL; i += 256)
        o[base + i] = __float2half_rn(x[base + i] * r * w[i]);
}

// ---------------- RoPE in-place on fp16 qkv ----------------
__global__ void rope_kernel(__half* __restrict__ qkv) {
    const int t   = blockIdx.x;
    const int pos = t & (SEQ - 1);
    const int h   = threadIdx.x >> 5;
    const int i   = threadIdx.x & 31;
    float invf = expf(-(2.0f * (float)i / (float)DH) * logf(10000.0f));
    float fr = (float)pos * invf;
    float s, c;
    sincosf(fr, &s, &c);
    __half* q = qkv + (size_t)t * (3 * TOT) + h * DH;
    float q1 = __half2float(q[i]), q2 = __half2float(q[i + 32]);
    q[i]      = __float2half_rn(q1 * c - q2 * s);
    q[i + 32] = __float2half_rn(q2 * c + q1 * s);
    __half* k = q + TOT;
    float k1 = __half2float(k[i]), k2 = __half2float(k[i + 32]);
    k[i]      = __float2half_rn(k1 * c - k2 * s);
    k[i + 32] = __float2half_rn(k2 * c + k1 * s);
}

// ---------------- FP16 mma GEMM, BM=128 BN=128 BK=64, 3-stage, ldmatrix ----------------
#define EPI_PLAIN  0
#define EPI_HALF   1
#define EPI_RES    2
#define EPI_SWIGLU 3

#define PW 36
#define GSTAGE_W (128 * PW)
#define GEMM_SMEM (6 * GSTAGE_W * 4)           // 108 KB

template<int EPI>
__global__ void __launch_bounds__(256, 2)
gemm_f16(const __half* __restrict__ A, int lda,
         const __half* __restrict__ B, int ldb,
         void* __restrict__ Cv, int ldc,
         const void* __restrict__ X, int K) {
    extern __shared__ uint32_t smw[];
    uint32_t* As = smw;
    uint32_t* Bs = smw + 3 * GSTAGE_W;

    const int tid  = threadIdx.x;
    const int lane = tid & 31;
    const int wid  = tid >> 5;
    const int wm_base = (wid >> 2) * 64;
    const int wn_base = (wid & 3) * 32;
    const int m0 = blockIdx.y * 128, n0 = blockIdx.x * 128;
    const int lr = lane >> 2, lc = lane & 3;

    const int a_off = (lane & 15) * PW + (lane >> 4) * 4;
    const int b_off = ((lane & 7) + ((lane >> 4) << 3)) * PW + (((lane >> 3) & 1) * 4);

    float acc[4][4][4];
    #pragma unroll
    for (int i = 0; i < 4; i++)
        #pragma unroll
        for (int j = 0; j < 4; j++)
            #pragma unroll
            for (int r = 0; r < 4; r++) acc[i][j][r] = 0.f;

    const int nt = K / 64;

    auto load_tile = [&](int stg, int kt) {
        uint32_t as_u = (uint32_t)__cvta_generic_to_shared(As + stg * GSTAGE_W);
        uint32_t bs_u = (uint32_t)__cvta_generic_to_shared(Bs + stg * GSTAGE_W);
        #pragma unroll
        for (int i = 0; i < 4; i++) {
            int c = tid + i * 256, row = c >> 3, sub = c & 7;
            uint32_t so = (uint32_t)(row * PW + sub * 4) * 4;
            cp16(as_u + so, A + (size_t)(m0 + row) * lda + kt + sub * 8);
            cp16(bs_u + so, B + (size_t)(n0 + row) * ldb + kt + sub * 8);
        }
        asm volatile("cp.async.commit_group;");
    };

    load_tile(0, 0);
    if (nt > 1) load_tile(1, 64);

    for (int t = 0; t < nt; t++) {
        if (t + 1 < nt) asm volatile("cp.async.wait_group 1;");
        else            asm volatile("cp.async.wait_group 0;");
        __syncthreads();
        if (t + 2 < nt) load_tile((t + 2) % 3, (t + 2) * 64);

        const uint32_t as_u = (uint32_t)__cvta_generic_to_shared(As + (t % 3) * GSTAGE_W);
        const uint32_t bs_u = (uint32_t)__cvta_generic_to_shared(Bs + (t % 3) * GSTAGE_W);
        #pragma unroll
        for (int ks = 0; ks < 4; ks++) {
            const int kw = ks * 8;
            uint32_t af[4][4];
            uint32_t bf[4][2];
            #pragma unroll
            for (int mi = 0; mi < 4; mi++)
                ldsm_x4(af[mi][0], af[mi][1], af[mi][2], af[mi][3],
                        as_u + (uint32_t)((wm_base + mi * 16) * PW + kw + a_off) * 4);
            #pragma unroll
            for (int njp = 0; njp < 2; njp++)
                ldsm_x4(bf[2*njp][0], bf[2*njp][1], bf[2*njp+1][0], bf[2*njp+1][1],
                        bs_u + (uint32_t)((wn_base + njp * 16) * PW + kw + b_off) * 4);
            #pragma unroll
            for (int mi = 0; mi < 4; mi++)
                #pragma unroll
                for (int nj = 0; nj < 4; nj++)
                    mma_f16(acc[mi][nj][0], acc[mi][nj][1], acc[mi][nj][2], acc[mi][nj][3],
                            af[mi][0], af[mi][1], af[mi][2], af[mi][3],
                            bf[nj][0], bf[nj][1]);
        }
        __syncthreads();
    }

    #pragma unroll
    for (int mi = 0; mi < 4; mi++) {
        int gm = m0 + wm_base + mi * 16 + lr;
        #pragma unroll
        for (int nj = 0; nj < 4; nj++) {
            int gn = n0 + wn_base + nj * 8 + 2 * lc;
            float2 v0 = make_float2(acc[mi][nj][0], acc[mi][nj][1]);
            float2 v1 = make_float2(acc[mi][nj][2], acc[mi][nj][3]);
            if (EPI == EPI_RES) {
                const float* Xf = (const float*)X;
                float2 r0 = *(const float2*)(Xf + (size_t)gm * ldc + gn);
                float2 r1 = *(const float2*)(Xf + (size_t)(gm + 8) * ldc + gn);
                v0.x += r0.x; v0.y += r0.y;
                v1.x += r1.x; v1.y += r1.y;
                float* C = (float*)Cv;
                *(float2*)(C + (size_t)gm * ldc + gn) = v0;
                *(float2*)(C + (size_t)(gm + 8) * ldc + gn) = v1;
            } else if (EPI == EPI_SWIGLU) {
                const __half* Xh = (const __half*)X;
                float2 g0 = __half22float2(*(const __half2*)(Xh + (size_t)gm * ldc + gn));
                float2 g1 = __half22float2(*(const __half2*)(Xh + (size_t)(gm + 8) * ldc + gn));
                __half* Ch = (__half*)Cv;
                *(__half2*)(Ch + (size_t)gm * ldc + gn) =
                    __floats2half2_rn(g0.x / (1.f + __expf(-g0.x)) * v0.x,
                                      g0.y / (1.f + __expf(-g0.y)) * v0.y);
                *(__half2*)(Ch + (size_t)(gm + 8) * ldc + gn) =
                    __floats2half2_rn(g1.x / (1.f + __expf(-g1.x)) * v1.x,
                                      g1.y / (1.f + __expf(-g1.y)) * v1.y);
            } else if (EPI == EPI_HALF) {
                __half* Ch = (__half*)Cv;
                *(__half2*)(Ch + (size_t)gm * ldc + gn) = __floats2half2_rn(v0.x, v0.y);
                *(__half2*)(Ch + (size_t)(gm + 8) * ldc + gn) = __floats2half2_rn(v1.x, v1.y);
            } else {
                float* C = (float*)Cv;
                *(float2*)(C + (size_t)gm * ldc + gn) = v0;
                *(float2*)(C + (size_t)(gm + 8) * ldc + gn) = v1;
            }
        }
    }
}

// ---------------- FP16 Flash attention, ldmatrix loads ----------------
#define FKPW 36
#define FTILE_W (64 * FKPW)
#define FLASH_SMEM (4 * FTILE_W * 4)   // 36 KB

__global__ void __launch_bounds__(256, 2)
flash_kernel(const __half* __restrict__ qkv, __half* __restrict__ attn) {
    extern __shared__ uint32_t smf[];
    uint32_t* Ks = smf;
    uint32_t* Vs = smf + 2 * FTILE_W;

    // heavy (large by) CTAs launch first
    const int by = (int)gridDim.x - 1 - (int)blockIdx.x;
    const int z  = blockIdx.y;
    const int b = z >> 4, h = z & 15;
    const int tid = threadIdx.x, lane = tid & 31, w = tid >> 5;
    const int lr = lane >> 2, lc = lane & 3;

    const __half* Qb = qkv + (size_t)b * SEQ * 3 * TOT + h * DH;
    const __half* Kb = Qb + TOT;
    const __half* Vb = Qb + 2 * TOT;
    const int q0 = by * 128 + w * 16;

    const int kb_off = ((lane & 7) + ((lane >> 4) << 3)) * FKPW + (((lane >> 3) & 1) * 4);
    const int v_off_h = (lane & 15) * 72 + (lane >> 4) * 8;

    const float sc = 0.18033688011f;
    uint32_t qf[4][4];
    {
        const __half* r0 = Qb + (size_t)(q0 + lr) * 3072;
        const __half* r1 = Qb + (size_t)(q0 + lr + 8) * 3072;
        #pragma unroll
        for (int ks = 0; ks < 4; ks++) {
            qf[ks][0] = scaleh2(*(const uint32_t*)(r0 + ks * 16 + 2 * lc    ), sc);
            qf[ks][1] = scaleh2(*(const uint32_t*)(r1 + ks * 16 + 2 * lc    ), sc);
            qf[ks][2] = scaleh2(*(const uint32_t*)(r0 + ks * 16 + 8 + 2 * lc), sc);
            qf[ks][3] = scaleh2(*(const uint32_t*)(r1 + ks * 16 + 8 + 2 * lc), sc);
        }
    }

    float m0 = -1e30f, m8 = -1e30f, l0 = 0.f, l8 = 0.f;
    float o[8][4];
    #pragma unroll
    for (int nd = 0; nd < 8; nd++)
        #pragma unroll
        for (int r = 0; r < 4; r++) o[nd][r] = 0.f;

    const int nt = 2 * by + 2;

    auto load_kv = [&](int t) {
        int buf = t & 1;
        uint32_t ku = (uint32_t)__cvta_generic_to_shared(Ks + buf * FTILE_W);
        uint32_t vu = (uint32_t)__cvta_generic_to_shared(Vs + buf * FTILE_W);
        int kv0 = t * 64;
        #pragma unroll
        for (int i = 0; i < 2; i++) {
            int c = tid + i * 256, r = c >> 3, cc = c & 7;
            uint32_t so = (uint32_t)(r * FKPW + cc * 4) * 4;
            cp16(ku + so, Kb + (size_t)(kv0 + r) * 3072 + cc * 8);
            cp16(vu + so, Vb + (size_t)(kv0 + r) * 3072 + cc * 8);
        }
        asm volatile("cp.async.commit_group;");
    };

    load_kv(0);

    for (int t = 0; t < nt; t++) {
        asm volatile("cp.async.wait_group 0;");
        __syncthreads();
        if (t + 1 < nt) load_kv(t + 1);

        const uint32_t ks_u = (uint32_t)__cvta_generic_to_shared(Ks + (t & 1) * FTILE_W);
        const uint32_t vs_u = (uint32_t)__cvta_generic_to_shared(Vs + (t & 1) * FTILE_W);

        float s[8][4];
        #pragma unroll
        for (int nj = 0; nj < 8; nj++)
            #pragma unroll
            for (int r = 0; r < 4; r++) s[nj][r] = 0.f;
        #pragma unroll
        for (int ks = 0; ks < 4; ks++) {
            const int kw = ks * 8;
            #pragma unroll
            for (int njp = 0; njp < 4; njp++) {
                uint32_t b00, b01, b10, b11;
                ldsm_x4(b00, b01, b10, b11,
                        ks_u + (uint32_t)(njp * 16 * FKPW + kw + kb_off) * 4);
                mma_f16(s[2*njp  ][0], s[2*njp  ][1], s[2*njp  ][2], s[2*njp  ][3],
                        qf[ks][0], qf[ks][1], qf[ks][2], qf[ks][3], b00, b01);
                mma_f16(s[2*njp+1][0], s[2*njp+1][1], s[2*njp+1][2], s[2*njp+1][3],
                        qf[ks][0], qf[ks][1], qf[ks][2], qf[ks][3], b10, b11);
            }
        }

        if (t >= 2 * by) {
            const int i0 = q0 + lr, i8 = i0 + 8;
            const int cb = t * 64;
            #pragma unroll
            for (int nj = 0; nj < 8; nj++) {
                int j0 = cb + nj * 8 + 2 * lc;
                if (j0     > i0) s[nj][0] = -1e30f;
                if (j0 + 1 > i0) s[nj][1] = -1e30f;
                if (j0     > i8) s[nj][2] = -1e30f;
                if (j0 + 1 > i8) s[nj][3] = -1e30f;
            }
        }

        float mx0 = -1e30f, mx8 = -1e30f;
        #pragma unroll
        for (int nj = 0; nj < 8; nj++) {
            mx0 = fmaxf(mx0, fmaxf(s[nj][0], s[nj][1]));
            mx8 = fmaxf(mx8, fmaxf(s[nj][2], s[nj][3]));
        }
        mx0 = fmaxf(mx0, __shfl_xor_sync(0xffffffffu, mx0, 1));
        mx0 = fmaxf(mx0, __shfl_xor_sync(0xffffffffu, mx0, 2));
        mx8 = fmaxf(mx8, __shfl_xor_sync(0xffffffffu, mx8, 1));
        mx8 = fmaxf(mx8, __shfl_xor_sync(0xffffffffu, mx8, 2));

        float mn0 = fmaxf(m0, mx0), mn8 = fmaxf(m8, mx8);
        float es0 = ex2(m0 - mn0), es8 = ex2(m8 - mn8);
        m0 = mn0; m8 = mn8;

        float sum0 = 0.f, sum8 = 0.f;
        #pragma unroll
        for (int nj = 0; nj < 8; nj++) {
            s[nj][0] = ex2(s[nj][0] - mn0);
            s[nj][1] = ex2(s[nj][1] - mn0);
            s[nj][2] = ex2(s[nj][2] - mn8);
            s[nj][3] = ex2(s[nj][3] - mn8);
            sum0 += s[nj][0] + s[nj][1];
            sum8 += s[nj][2] + s[nj][3];
        }
        sum0 += __shfl_xor_sync(0xffffffffu, sum0, 1);
        sum0 += __shfl_xor_sync(0xffffffffu, sum0, 2);
        sum8 += __shfl_xor_sync(0xffffffffu, sum8, 1);
        sum8 += __shfl_xor_sync(0xffffffffu, sum8, 2);
        l0 = l0 * es0 + sum0;
        l8 = l8 * es8 + sum8;

        #pragma unroll
        for (int nd = 0; nd < 8; nd++) {
            o[nd][0] *= es0; o[nd][1] *= es0;
            o[nd][2] *= es8; o[nd][3] *= es8;
        }

        #pragma unroll
        for (int tt = 0; tt < 4; tt++) {
            uint32_t a0 = packh2(s[2*tt    ][0], s[2*tt    ][1]);
            uint32_t a1 = packh2(s[2*tt    ][2], s[2*tt    ][3]);
            uint32_t a2 = packh2(s[2*tt + 1][0], s[2*tt + 1][1]);
            uint32_t a3 = packh2(s[2*tt + 1][2], s[2*tt + 1][3]);
            #pragma unroll
            for (int ndp = 0; ndp < 4; ndp++) {
                uint32_t b00, b01, b10, b11;
                ldsm_x4_t(b00, b01, b10, b11,
                          vs_u + (uint32_t)(tt * 16 * 72 + ndp * 16 + v_off_h) * 2);
                mma_f16(o[2*ndp  ][0], o[2*ndp  ][1], o[2*ndp  ][2], o[2*ndp  ][3],
                        a0, a1, a2, a3, b00, b01);
                mma_f16(o[2*ndp+1][0], o[2*ndp+1][1], o[2*ndp+1][2], o[2*ndp+1][3],
                        a0, a1, a2, a3, b10, b11);
            }
        }
        __syncthreads();
    }

    const float inv0 = 1.f / l0, inv8 = 1.f / l8;
    const size_t trow = (size_t)b * SEQ + q0;
    __half* ob0 = attn + (trow + lr    ) * TOT + h * DH;
    __half* ob8 = attn + (trow + lr + 8) * TOT + h * DH;
    #pragma unroll
    for (int nd = 0; nd < 8; nd++) {
        int col = nd * 8 + 2 * lc;
        *(__half2*)(ob0 + col) = __floats2half2_rn(o[nd][0] * inv0, o[nd][1] * inv0);
        *(__half2*)(ob8 + col) = __floats2half2_rn(o[nd][2] * inv8, o[nd][3] * inv8);
    }
}

// ---------------- launch ----------------
extern "C" void kernel_launch(void* const* d_in, const int* in_sizes, int n_in,
                              void* d_out, int out_size) {
    const float* x      = (const float*)d_in[0];
    const float* w_ln1  = (const float*)d_in[1];
    const float* w_qkv  = (const float*)d_in[2];
    const float* w_out  = (const float*)d_in[3];
    const float* w_ln2  = (const float*)d_in[4];
    const float* w_gate = (const float*)d_in[5];
    const float* w_up   = (const float*)d_in[6];
    const float* w_down = (const float*)d_in[7];
    float* out = (float*)d_out;

    void* p;
    cudaGetSymbolAddress(&p, g_hh);    __half* h    = (__half*)p;
    cudaGetSymbolAddress(&p, g_qkvh);  __half* qkv  = (__half*)p;
    cudaGetSymbolAddress(&p, g_attnh); __half* attn = (__half*)p;
    cudaGetSymbolAddress(&p, g_x2);    float*  x2   = (float*)p;
    cudaGetSymbolAddress(&p, g_gateh); __half* gateh= (__half*)p;
    cudaGetSymbolAddress(&p, g_ffh);   __half* ffh  = (__half*)p;
    cudaGetSymbolAddress(&p, g_wh);    __half* wh   = (__half*)p;

    __half* wqkv_h  = wh;
    __half* wout_h  = wqkv_h + 3*1024*1024;
    __half* wgate_h = wout_h + 1024*1024;
    __half* wup_h   = wgate_h + 4*1024*1024;
    __half* wdown_h = wup_h + 4*1024*1024;

    cudaFuncSetAttribute(gemm_f16<EPI_HALF>,   cudaFuncAttributeMaxDynamicSharedMemorySize, GEMM_SMEM);
    cudaFuncSetAttribute(gemm_f16<EPI_RES>,    cudaFuncAttributeMaxDynamicSharedMemorySize, GEMM_SMEM);
    cudaFuncSetAttribute(gemm_f16<EPI_SWIGLU>, cudaFuncAttributeMaxDynamicSharedMemorySize, GEMM_SMEM);
    cudaFuncSetAttribute(flash_kernel, cudaFuncAttributeMaxDynamicSharedMemorySize, FLASH_SMEM);

    // 0) convert all weights to fp16
    to_half_all<<<512, 256>>>(w_qkv, w_out, w_gate, w_up, w_down, wh);

    // 1) h = rmsnorm(x, w_ln1) -> fp16
    rmsnorm_kernel<<<NTOK, 256>>>(x, w_ln1, h);

    // 2) qkv = h @ w_qkv^T -> fp16
    gemm_f16<EPI_HALF><<<dim3(3*TOT/128, NTOK/128), 256, GEMM_SMEM>>>(
        h, D_MODEL, wqkv_h, D_MODEL, qkv, 3*TOT, nullptr, D_MODEL);

    // 3) RoPE (fp16 in-place)
    rope_kernel<<<NTOK, 512>>>(qkv);

    // 4) flash attention -> attn (fp16)
    flash_kernel<<<dim3(SEQ/128, BATCH*NH), 256, FLASH_SMEM>>>(qkv, attn);

    // 5) x2 = x + attn @ w_out^T   (BM=128, proven config)
    gemm_f16<EPI_RES><<<dim3(D_MODEL/128, NTOK/128), 256, GEMM_SMEM>>>(
        attn, TOT, wout_h, TOT, x2, D_MODEL, x, TOT);

    // 6) h = rmsnorm(x2, w_ln2) -> fp16
    rmsnorm_kernel<<<NTOK, 256>>>(x2, w_ln2, h);

    // 7) gate = h @ w_gate^T -> fp16; up-proj fused SwiGLU -> ffh (fp16)
    gemm_f16<EPI_HALF><<<dim3(D_FF/128, NTOK/128), 256, GEMM_SMEM>>>(
        h, D_MODEL, wgate_h, D_MODEL, gateh, D_FF, nullptr, D_MODEL);
    gemm_f16<EPI_SWIGLU><<<dim3(D_FF/128, NTOK/128), 256, GEMM_SMEM>>>(
        h, D_MODEL, wup_h, D_MODEL, ffh, D_FF, gateh, D_MODEL);

    // 8) out = x2 + ffh @ w_down^T   (BM=128)
    gemm_f16<EPI_RES><<<dim3(D_MODEL/128, NTOK/128), 256, GEMM_SMEM>>>(
        ffh, D_FF, wdown_h, D_FF, out, D_MODEL, x2, D_FF);
}

// round 16
// speedup vs baseline: 1.0953x; 1.0240x over previous
#include <cuda_runtime.h>
#include <cuda_fp16.h>
#include <math.h>
#include <stdint.h>

// ---------------- problem constants ----------------
#define D_MODEL 1024
#define D_FF    4096
#define NH      16
#define DH      64
#define TOT     1024
#define BATCH   2
#define SEQ     2048
#define NTOK    (BATCH*SEQ)

// ---------------- scratch ----------------
__device__ __half g_hh  [(size_t)NTOK * D_MODEL];
__device__ __half g_qkvh[(size_t)NTOK * 3 * TOT];
__device__ __half g_attnh[(size_t)NTOK * TOT];
__device__ float  g_x2  [(size_t)NTOK * D_MODEL];
__device__ __half g_ffh [(size_t)NTOK * D_FF];
__device__ __half g_wh  [(size_t)16 * 1024 * 1024];

// ---------------- helpers ----------------
__device__ __forceinline__ void cp16(uint32_t dst, const void* src) {
    asm volatile("cp.async.cg.shared.global [%0], [%1], 16;" :: "r"(dst), "l"(src));
}
__device__ __forceinline__ float ex2(float x) {
    float r;
    asm("ex2.approx.ftz.f32 %0, %1;" : "=f"(r) : "f"(x));
    return r;
}
__device__ __forceinline__ uint32_t packh2(float lo, float hi) {
    __half2 h = __floats2half2_rn(lo, hi);
    return *reinterpret_cast<uint32_t*>(&h);
}
__device__ __forceinline__ uint32_t scaleh2(uint32_t w, float sc) {
    __half2 h = *reinterpret_cast<__half2*>(&w);
    float2 f = __half22float2(h);
    return packh2(f.x * sc, f.y * sc);
}
__device__ __forceinline__ void mma_f16(float& c0, float& c1, float& c2, float& c3,
                                        uint32_t a0, uint32_t a1, uint32_t a2, uint32_t a3,
                                        uint32_t b0, uint32_t b1) {
    asm volatile(
        "mma.sync.aligned.m16n8k16.row.col.f32.f16.f16.f32 "
        "{%0,%1,%2,%3}, {%4,%5,%6,%7}, {%8,%9}, {%0,%1,%2,%3};"
        : "+f"(c0), "+f"(c1), "+f"(c2), "+f"(c3)
        : "r"(a0), "r"(a1), "r"(a2), "r"(a3), "r"(b0), "r"(b1));
}
__device__ __forceinline__ void ldsm_x4(uint32_t& r0, uint32_t& r1, uint32_t& r2, uint32_t& r3,
                                        uint32_t addr) {
    asm volatile("ldmatrix.sync.aligned.m8n8.x4.shared.b16 {%0,%1,%2,%3}, [%4];"
                 : "=r"(r0), "=r"(r1), "=r"(r2), "=r"(r3) : "r"(addr));
}
__device__ __forceinline__ void ldsm_x4_t(uint32_t& r0, uint32_t& r1, uint32_t& r2, uint32_t& r3,
                                          uint32_t addr) {
    asm volatile("ldmatrix.sync.aligned.m8n8.x4.trans.shared.b16 {%0,%1,%2,%3}, [%4];"
                 : "=r"(r0), "=r"(r1), "=r"(r2), "=r"(r3) : "r"(addr));
}

// ---------------- block reduction ----------------
__device__ __forceinline__ float block_reduce_sum(float v) {
    __shared__ float sh[33];
    int lane = threadIdx.x & 31, wid = threadIdx.x >> 5;
    #pragma unroll
    for (int o = 16; o; o >>= 1) v += __shfl_xor_sync(0xffffffffu, v, o);
    if (lane == 0) sh[wid] = v;
    __syncthreads();
    if (wid == 0) {
        v = (lane < (blockDim.x >> 5)) ? sh[lane] : 0.f;
        #pragma unroll
        for (int o = 16; o; o >>= 1) v += __shfl_xor_sync(0xffffffffu, v, o);
        if (lane == 0) sh[32] = v;
    }
    __syncthreads();
    float r = sh[32];
    __syncthreads();
    return r;
}

// ---------------- weights fp32 -> fp16, gate/up column-interleaved ----------------
// fp16 layout (halves): qkv [0,3M) | out [3M,4M) | wgu interleaved [4M,12M) | down [12M,16M)
// wgu row 2n = w_gate row n, row 2n+1 = w_up row n.
__global__ void to_half_all(const float* __restrict__ wqkv, const float* __restrict__ wout,
                            const float* __restrict__ wgate, const float* __restrict__ wup,
                            const float* __restrict__ wdown, __half* __restrict__ out) {
    int idx = blockIdx.x * blockDim.x + threadIdx.x;
    const int stride = gridDim.x * blockDim.x;
    for (; idx < 4 * 1024 * 1024; idx += stride) {    // float4 units
        const float* src;
        size_t local, dstl, ob;
        if (idx < 768 * 1024) {                        // qkv
            src = wqkv;  local = idx;  dstl = local;  ob = 0;
        } else if (idx < 1024 * 1024) {                // out
            src = wout;  local = idx - 768 * 1024;  dstl = local;  ob = (size_t)3 * 1024 * 1024;
        } else if (idx < 2 * 1024 * 1024) {            // gate -> even rows of wgu
            src = wgate; local = idx - 1024 * 1024;
            dstl = (local >> 8) * 512 + (local & 255);
            ob = (size_t)4 * 1024 * 1024;
        } else if (idx < 3 * 1024 * 1024) {            // up -> odd rows of wgu
            src = wup;   local = idx - 2 * 1024 * 1024;
            dstl = (local >> 8) * 512 + 256 + (local & 255);
            ob = (size_t)4 * 1024 * 1024;
        } else {                                       // down
            src = wdown; local = idx - 3 * 1024 * 1024;  dstl = local;
            ob = (size_t)12 * 1024 * 1024;
        }
        float4 v = ((const float4*)src)[local];
        __half2* o2 = (__half2*)(out + ob);
        o2[dstl * 2    ] = __floats2half2_rn(v.x, v.y);
        o2[dstl * 2 + 1] = __floats2half2_rn(v.z, v.w);
    }
}

// ---------------- RMSNorm -> fp16 ----------------
__global__ void rmsnorm_kernel(const float* __restrict__ x,
                               const float* __restrict__ w,
                               __half* __restrict__ o) {
    const size_t base = (size_t)blockIdx.x * D_MODEL;
    float ss = 0.f;
    for (int i = threadIdx.x; i < D_MODEL; i += 256) {
        float v = x[base + i];
        ss += v * v;
    }
    ss = block_reduce_sum(ss);
    float r = rsqrtf(ss * (1.0f / D_MODEL) + 1e-6f);
    for (int i = threadIdx.x; i < D_MODEL; i += 256)
        o[base + i] = __float2half_rn(x[base + i] * r * w[i]);
}

// ---------------- RoPE in-place on fp16 qkv ----------------
__global__ void rope_kernel(__half* __restrict__ qkv) {
    const int t   = blockIdx.x;
    const int pos = t & (SEQ - 1);
    const int h   = threadIdx.x >> 5;
    const int i   = threadIdx.x & 31;
    float invf = expf(-(2.0f * (float)i / (float)DH) * logf(10000.0f));
    float fr = (float)pos * invf;
    float s, c;
    sincosf(fr, &s, &c);
    __half* q = qkv + (size_t)t * (3 * TOT) + h * DH;
    float q1 = __half2float(q[i]), q2 = __half2float(q[i + 32]);
    q[i]      = __float2half_rn(q1 * c - q2 * s);
    q[i + 32] = __float2half_rn(q2 * c + q1 * s);
    __half* k = q + TOT;
    float k1 = __half2float(k[i]), k2 = __half2float(k[i + 32]);
    k[i]      = __float2half_rn(k1 * c - k2 * s);
    k[i + 32] = __float2half_rn(k2 * c + k1 * s);
}

// ---------------- FP16 mma GEMM, BM=128 BN=128 BK=64, 3-stage, ldmatrix ----------------
// EPI 0: fp32 plain  EPI 1: fp16 store  EPI 2: fp32 + X residual
// EPI 4: interleaved gate/up -> fp16 silu(even)*odd, C has ldc cols of D_FF
#define EPI_PLAIN  0
#define EPI_HALF   1
#define EPI_RES    2
#define EPI_GLU    4

#define PW 36
#define GSTAGE_W (128 * PW)
#define GEMM_SMEM (6 * GSTAGE_W * 4)           // 108 KB

template<int EPI>
__global__ void __launch_bounds__(256, 2)
gemm_f16(const __half* __restrict__ A, int lda,
         const __half* __restrict__ B, int ldb,
         void* __restrict__ Cv, int ldc,
         const void* __restrict__ X, int K) {
    extern __shared__ uint32_t smw[];
    uint32_t* As = smw;
    uint32_t* Bs = smw + 3 * GSTAGE_W;

    const int tid  = threadIdx.x;
    const int lane = tid & 31;
    const int wid  = tid >> 5;
    const int wm_base = (wid >> 2) * 64;
    const int wn_base = (wid & 3) * 32;
    const int m0 = blockIdx.y * 128, n0 = blockIdx.x * 128;
    const int lr = lane >> 2, lc = lane & 3;

    const int a_off = (lane & 15) * PW + (lane >> 4) * 4;
    const int b_off = ((lane & 7) + ((lane >> 4) << 3)) * PW + (((lane >> 3) & 1) * 4);

    float acc[4][4][4];
    #pragma unroll
    for (int i = 0; i < 4; i++)
        #pragma unroll
        for (int j = 0; j < 4; j++)
            #pragma unroll
            for (int r = 0; r < 4; r++) acc[i][j][r] = 0.f;

    const int nt = K / 64;

    auto load_tile = [&](int stg, int kt) {
        uint32_t as_u = (uint32_t)__cvta_generic_to_shared(As + stg * GSTAGE_W);
        uint32_t bs_u = (uint32_t)__cvta_generic_to_shared(Bs + stg * GSTAGE_W);
        #pragma unroll
        for (int i = 0; i < 4; i++) {
            int c = tid + i * 256, row = c >> 3, sub = c & 7;
            uint32_t so = (uint32_t)(row * PW + sub * 4) * 4;
            cp16(as_u + so, A + (size_t)(m0 + row) * lda + kt + sub * 8);
            cp16(bs_u + so, B + (size_t)(n0 + row) * ldb + kt + sub * 8);
        }
        asm volatile("cp.async.commit_group;");
    };

    load_tile(0, 0);
    if (nt > 1) load_tile(1, 64);

    for (int t = 0; t < nt; t++) {
        if (t + 1 < nt) asm volatile("cp.async.wait_group 1;");
        else            asm volatile("cp.async.wait_group 0;");
        __syncthreads();
        if (t + 2 < nt) load_tile((t + 2) % 3, (t + 2) * 64);

        const uint32_t as_u = (uint32_t)__cvta_generic_to_shared(As + (t % 3) * GSTAGE_W);
        const uint32_t bs_u = (uint32_t)__cvta_generic_to_shared(Bs + (t % 3) * GSTAGE_W);
        #pragma unroll
        for (int ks = 0; ks < 4; ks++) {
            const int kw = ks * 8;
            uint32_t af[4][4];
            uint32_t bf[4][2];
            #pragma unroll
            for (int mi = 0; mi < 4; mi++)
                ldsm_x4(af[mi][0], af[mi][1], af[mi][2], af[mi][3],
                        as_u + (uint32_t)((wm_base + mi * 16) * PW + kw + a_off) * 4);
            #pragma unroll
            for (int njp = 0; njp < 2; njp++)
                ldsm_x4(bf[2*njp][0], bf[2*njp][1], bf[2*njp+1][0], bf[2*njp+1][1],
                        bs_u + (uint32_t)((wn_base + njp * 16) * PW + kw + b_off) * 4);
            #pragma unroll
            for (int mi = 0; mi < 4; mi++)
                #pragma unroll
                for (int nj = 0; nj < 4; nj++)
                    mma_f16(acc[mi][nj][0], acc[mi][nj][1], acc[mi][nj][2], acc[mi][nj][3],
                            af[mi][0], af[mi][1], af[mi][2], af[mi][3],
                            bf[nj][0], bf[nj][1]);
        }
        __syncthreads();
    }

    #pragma unroll
    for (int mi = 0; mi < 4; mi++) {
        int gm = m0 + wm_base + mi * 16 + lr;
        #pragma unroll
        for (int nj = 0; nj < 4; nj++) {
            int gn = n0 + wn_base + nj * 8 + 2 * lc;
            float2 v0 = make_float2(acc[mi][nj][0], acc[mi][nj][1]);
            float2 v1 = make_float2(acc[mi][nj][2], acc[mi][nj][3]);
            if (EPI == EPI_RES) {
                const float* Xf = (const float*)X;
                float2 r0 = *(const float2*)(Xf + (size_t)gm * ldc + gn);
                float2 r1 = *(const float2*)(Xf + (size_t)(gm + 8) * ldc + gn);
                v0.x += r0.x; v0.y += r0.y;
                v1.x += r1.x; v1.y += r1.y;
                float* C = (float*)Cv;
                *(float2*)(C + (size_t)gm * ldc + gn) = v0;
                *(float2*)(C + (size_t)(gm + 8) * ldc + gn) = v1;
            } else if (EPI == EPI_GLU) {
                // interleaved columns: even = gate, odd = up; logical col = gn/2
                __half* Ch = (__half*)Cv;
                int gnn = gn >> 1;
                Ch[(size_t)gm * ldc + gnn] =
                    __float2half_rn(v0.x / (1.f + __expf(-v0.x)) * v0.y);
                Ch[(size_t)(gm + 8) * ldc + gnn] =
                    __float2half_rn(v1.x / (1.f + __expf(-v1.x)) * v1.y);
            } else if (EPI == EPI_HALF) {
                __half* Ch = (__half*)Cv;
                *(__half2*)(Ch + (size_t)gm * ldc + gn) = __floats2half2_rn(v0.x, v0.y);
                *(__half2*)(Ch + (size_t)(gm + 8) * ldc + gn) = __floats2half2_rn(v1.x, v1.y);
            } else {
                float* C = (float*)Cv;
                *(float2*)(C + (size_t)gm * ldc + gn) = v0;
                *(float2*)(C + (size_t)(gm + 8) * ldc + gn) = v1;
            }
        }
    }
}

// ---------------- FP16 Flash attention, ldmatrix loads ----------------
#define FKPW 36
#define FTILE_W (64 * FKPW)
#define FLASH_SMEM (4 * FTILE_W * 4)   // 36 KB

__global__ void __launch_bounds__(256, 2)
flash_kernel(const __half* __restrict__ qkv, __half* __restrict__ attn) {
    extern __shared__ uint32_t smf[];
    uint32_t* Ks = smf;
    uint32_t* Vs = smf + 2 * FTILE_W;

    const int by = (int)gridDim.x - 1 - (int)blockIdx.x;   // heavy CTAs first
    const int z  = blockIdx.y;
    const int b = z >> 4, h = z & 15;
    const int tid = threadIdx.x, lane = tid & 31, w = tid >> 5;
    const int lr = lane >> 2, lc = lane & 3;

    const __half* Qb = qkv + (size_t)b * SEQ * 3 * TOT + h * DH;
    const __half* Kb = Qb + TOT;
    const __half* Vb = Qb + 2 * TOT;
    const int q0 = by * 128 + w * 16;

    const int kb_off = ((lane & 7) + ((lane >> 4) << 3)) * FKPW + (((lane >> 3) & 1) * 4);
    const int v_off_h = (lane & 15) * 72 + (lane >> 4) * 8;

    const float sc = 0.18033688011f;
    uint32_t qf[4][4];
    {
        const __half* r0 = Qb + (size_t)(q0 + lr) * 3072;
        const __half* r1 = Qb + (size_t)(q0 + lr + 8) * 3072;
        #pragma unroll
        for (int ks = 0; ks < 4; ks++) {
            qf[ks][0] = scaleh2(*(const uint32_t*)(r0 + ks * 16 + 2 * lc    ), sc);
            qf[ks][1] = scaleh2(*(const uint32_t*)(r1 + ks * 16 + 2 * lc    ), sc);
            qf[ks][2] = scaleh2(*(const uint32_t*)(r0 + ks * 16 + 8 + 2 * lc), sc);
            qf[ks][3] = scaleh2(*(const uint32_t*)(r1 + ks * 16 + 8 + 2 * lc), sc);
        }
    }

    float m0 = -1e30f, m8 = -1e30f, l0 = 0.f, l8 = 0.f;
    float o[8][4];
    #pragma unroll
    for (int nd = 0; nd < 8; nd++)
        #pragma unroll
        for (int r = 0; r < 4; r++) o[nd][r] = 0.f;

    const int nt = 2 * by + 2;

    auto load_kv = [&](int t) {
        int buf = t & 1;
        uint32_t ku = (uint32_t)__cvta_generic_to_shared(Ks + buf * FTILE_W);
        uint32_t vu = (uint32_t)__cvta_generic_to_shared(Vs + buf * FTILE_W);
        int kv0 = t * 64;
        #pragma unroll
        for (int i = 0; i < 2; i++) {
            int c = tid + i * 256, r = c >> 3, cc = c & 7;
            uint32_t so = (uint32_t)(r * FKPW + cc * 4) * 4;
            cp16(ku + so, Kb + (size_t)(kv0 + r) * 3072 + cc * 8);
            cp16(vu + so, Vb + (size_t)(kv0 + r) * 3072 + cc * 8);
        }
        asm volatile("cp.async.commit_group;");
    };

    load_kv(0);

    for (int t = 0; t < nt; t++) {
        asm volatile("cp.async.wait_group 0;");
        __syncthreads();
        if (t + 1 < nt) load_kv(t + 1);

        const uint32_t ks_u = (uint32_t)__cvta_generic_to_shared(Ks + (t & 1) * FTILE_W);
        const uint32_t vs_u = (uint32_t)__cvta_generic_to_shared(Vs + (t & 1) * FTILE_W);

        float s[8][4];
        #pragma unroll
        for (int nj = 0; nj < 8; nj++)
            #pragma unroll
            for (int r = 0; r < 4; r++) s[nj][r] = 0.f;
        #pragma unroll
        for (int ks = 0; ks < 4; ks++) {
            const int kw = ks * 8;
            #pragma unroll
            for (int njp = 0; njp < 4; njp++) {
                uint32_t b00, b01, b10, b11;
                ldsm_x4(b00, b01, b10, b11,
                        ks_u + (uint32_t)(njp * 16 * FKPW + kw + kb_off) * 4);
                mma_f16(s[2*njp  ][0], s[2*njp  ][1], s[2*njp  ][2], s[2*njp  ][3],
                        qf[ks][0], qf[ks][1], qf[ks][2], qf[ks][3], b00, b01);
                mma_f16(s[2*njp+1][0], s[2*njp+1][1], s[2*njp+1][2], s[2*njp+1][3],
                        qf[ks][0], qf[ks][1], qf[ks][2], qf[ks][3], b10, b11);
            }
        }

        if (t >= 2 * by) {
            const int i0 = q0 + lr, i8 = i0 + 8;
            const int cb = t * 64;
            #pragma unroll
            for (int nj = 0; nj < 8; nj++) {
                int j0 = cb + nj * 8 + 2 * lc;
                if (j0     > i0) s[nj][0] = -1e30f;
                if (j0 + 1 > i0) s[nj][1] = -1e30f;
                if (j0     > i8) s[nj][2] = -1e30f;
                if (j0 + 1 > i8) s[nj][3] = -1e30f;
            }
        }

        float mx0 = -1e30f, mx8 = -1e30f;
        #pragma unroll
        for (int nj = 0; nj < 8; nj++) {
            mx0 = fmaxf(mx0, fmaxf(s[nj][0], s[nj][1]));
            mx8 = fmaxf(mx8, fmaxf(s[nj][2], s[nj][3]));
        }
        mx0 = fmaxf(mx0, __shfl_xor_sync(0xffffffffu, mx0, 1));
        mx0 = fmaxf(mx0, __shfl_xor_sync(0xffffffffu, mx0, 2));
        mx8 = fmaxf(mx8, __shfl_xor_sync(0xffffffffu, mx8, 1));
        mx8 = fmaxf(mx8, __shfl_xor_sync(0xffffffffu, mx8, 2));

        float mn0 = fmaxf(m0, mx0), mn8 = fmaxf(m8, mx8);
        float es0 = ex2(m0 - mn0), es8 = ex2(m8 - mn8);
        m0 = mn0; m8 = mn8;

        float sum0 = 0.f, sum8 = 0.f;
        #pragma unroll
        for (int nj = 0; nj < 8; nj++) {
            s[nj][0] = ex2(s[nj][0] - mn0);
            s[nj][1] = ex2(s[nj][1] - mn0);
            s[nj][2] = ex2(s[nj][2] - mn8);
            s[nj][3] = ex2(s[nj][3] - mn8);
            sum0 += s[nj][0] + s[nj][1];
            sum8 += s[nj][2] + s[nj][3];
        }
        sum0 += __shfl_xor_sync(0xffffffffu, sum0, 1);
        sum0 += __shfl_xor_sync(0xffffffffu, sum0, 2);
        sum8 += __shfl_xor_sync(0xffffffffu, sum8, 1);
        sum8 += __shfl_xor_sync(0xffffffffu, sum8, 2);
        l0 = l0 * es0 + sum0;
        l8 = l8 * es8 + sum8;

        #pragma unroll
        for (int nd = 0; nd < 8; nd++) {
            o[nd][0] *= es0; o[nd][1] *= es0;
            o[nd][2] *= es8; o[nd][3] *= es8;
        }

        #pragma unroll
        for (int tt = 0; tt < 4; tt++) {
            uint32_t a0 = packh2(s[2*tt    ][0], s[2*tt    ][1]);
            uint32_t a1 = packh2(s[2*tt    ][2], s[2*tt    ][3]);
            uint32_t a2 = packh2(s[2*tt + 1][0], s[2*tt + 1][1]);
            uint32_t a3 = packh2(s[2*tt + 1][2], s[2*tt + 1][3]);
            #pragma unroll
            for (int ndp = 0; ndp < 4; ndp++) {
                uint32_t b00, b01, b10, b11;
                ldsm_x4_t(b00, b01, b10, b11,
                          vs_u + (uint32_t)(tt * 16 * 72 + ndp * 16 + v_off_h) * 2);
                mma_f16(o[2*ndp  ][0], o[2*ndp  ][1], o[2*ndp  ][2], o[2*ndp  ][3],
                        a0, a1, a2, a3, b00, b01);
                mma_f16(o[2*ndp+1][0], o[2*ndp+1][1], o[2*ndp+1][2], o[2*ndp+1][3],
                        a0, a1, a2, a3, b10, b11);
            }
        }
        __syncthreads();
    }

    const float inv0 = 1.f / l0, inv8 = 1.f / l8;
    const size_t trow = (size_t)b * SEQ + q0;
    __half* ob0 = attn + (trow + lr    ) * TOT + h * DH;
    __half* ob8 = attn + (trow + lr + 8) * TOT + h * DH;
    #pragma unroll
    for (int nd = 0; nd < 8; nd++) {
        int col = nd * 8 + 2 * lc;
        *(__half2*)(ob0 + col) = __floats2half2_rn(o[nd][0] * inv0, o[nd][1] * inv0);
        *(__half2*)(ob8 + col) = __floats2half2_rn(o[nd][2] * inv8, o[nd][3] * inv8);
    }
}

// ---------------- launch ----------------
extern "C" void kernel_launch(void* const* d_in, const int* in_sizes, int n_in,
                              void* d_out, int out_size) {
    const float* x      = (const float*)d_in[0];
    const float* w_ln1  = (const float*)d_in[1];
    const float* w_qkv  = (const float*)d_in[2];
    const float* w_out  = (const float*)d_in[3];
    const float* w_ln2  = (const float*)d_in[4];
    const float* w_gate = (const float*)d_in[5];
    const float* w_up   = (const float*)d_in[6];
    const float* w_down = (const float*)d_in[7];
    float* out = (float*)d_out;

    void* p;
    cudaGetSymbolAddress(&p, g_hh);    __half* h    = (__half*)p;
    cudaGetSymbolAddress(&p, g_qkvh);  __half* qkv  = (__half*)p;
    cudaGetSymbolAddress(&p, g_attnh); __half* attn = (__half*)p;
    cudaGetSymbolAddress(&p, g_x2);    float*  x2   = (float*)p;
    cudaGetSymbolAddress(&p, g_ffh);   __half* ffh  = (__half*)p;
    cudaGetSymbolAddress(&p, g_wh);    __half* wh   = (__half*)p;

    __half* wqkv_h  = wh;
    __half* wout_h  = wqkv_h + 3*1024*1024;
    __half* wgu_h   = wout_h + 1024*1024;      // interleaved gate/up [8192 x 1024]
    __half* wdown_h = wgu_h + 8*1024*1024;

    cudaFuncSetAttribute(gemm_f16<EPI_HALF>, cudaFuncAttributeMaxDynamicSharedMemorySize, GEMM_SMEM);
    cudaFuncSetAttribute(gemm_f16<EPI_RES>,  cudaFuncAttributeMaxDynamicSharedMemorySize, GEMM_SMEM);
    cudaFuncSetAttribute(gemm_f16<EPI_GLU>,  cudaFuncAttributeMaxDynamicSharedMemorySize, GEMM_SMEM);
    cudaFuncSetAttribute(flash_kernel, cudaFuncAttributeMaxDynamicSharedMemorySize, FLASH_SMEM);

    // 0) convert + interleave weights
    to_half_all<<<512, 256>>>(w_qkv, w_out, w_gate, w_up, w_down, wh);

    // 1) h = rmsnorm(x, w_ln1) -> fp16
    rmsnorm_kernel<<<NTOK, 256>>>(x, w_ln1, h);

    // 2) qkv = h @ w_qkv^T -> fp16
    gemm_f16<EPI_HALF><<<dim3(3*TOT/128, NTOK/128), 256, GEMM_SMEM>>>(
        h, D_MODEL, wqkv_h, D_MODEL, qkv, 3*TOT, nullptr, D_MODEL);

    // 3) RoPE (fp16 in-place)
    rope_kernel<<<NTOK, 512>>>(qkv);

    // 4) flash attention -> attn (fp16)
    flash_kernel<<<dim3(SEQ/128, BATCH*NH), 256, FLASH_SMEM>>>(qkv, attn);

    // 5) x2 = x + attn @ w_out^T
    gemm_f16<EPI_RES><<<dim3(D_MODEL/128, NTOK/128), 256, GEMM_SMEM>>>(
        attn, TOT, wout_h, TOT, x2, D_MODEL, x, TOT);

    // 6) h = rmsnorm(x2, w_ln2) -> fp16
    rmsnorm_kernel<<<NTOK, 256>>>(x2, w_ln2, h);

    // 7) fused gate+up+SwiGLU: ffh = fp16(silu(h@wg^T) * (h@wu^T)) via interleaved N=8192
    gemm_f16<EPI_GLU><<<dim3(2*D_FF/128, NTOK/128), 256, GEMM_SMEM>>>(
        h, D_MODEL, wgu_h, D_MODEL, ffh, D_FF, nullptr, D_MODEL);

    // 8) out = x2 + ffh @ w_down^T
    gemm_f16<EPI_RES><<<dim3(D_MODEL/128, NTOK/128), 256, GEMM_SMEM>>>(
        ffh, D_FF, wdown_h, D_FF, out, D_MODEL, x2, D_FF);
}